// round 7
// baseline (speedup 1.0000x reference)
#include <cuda_runtime.h>
#include <cuda_bf16.h>
#include <cuda_fp8.h>
#include <stdint.h>
#include <math.h>

#define NTOK 2048
#define DMODEL 1024
#define NHEAD 16
#define NKV 4
#define HEADDIM 64
#define FFN 4096
#define VOCAB 32000
#define NLAYER 4
#define SEQ 1024
#define KVDIM (NKV * HEADDIM)   // 256

#define EMB_N (VOCAB * DMODEL)
#define QW_N (NLAYER * DMODEL * DMODEL)
#define KW_N (NLAYER * KVDIM * DMODEL)
#define W1_N (NLAYER * FFN * DMODEL)

// scales: fp8 hi-plane = S * x ; fp8 lo-plane = S * 256 * (x - bf16(x))
#define SW_W 256.0f     // weights (~0.02 rms -> ~5)
#define SA_H 16.0f      // rmsnorm / attention outputs (~1 rms -> ~16)
#define SA_UP 32.0f     // swiglu product (~0.2 rms -> ~6)

// ---------------- scratch (device globals; no runtime allocation) ----------------
__device__ float g_x[NTOK * DMODEL];
__device__ float g_q[NTOK * DMODEL];
__device__ float g_k[NTOK * KVDIM];
__device__ float g_v[NTOK * KVDIM];
__device__ float g_gate[NTOK * FFN];

__device__ __nv_bfloat16 g_h_h[NTOK * DMODEL];
__device__ uint8_t g_h_8h[NTOK * DMODEL], g_h_8l[NTOK * DMODEL];
__device__ __nv_bfloat16 g_o_h[NTOK * DMODEL];
__device__ uint8_t g_o_8h[NTOK * DMODEL], g_o_8l[NTOK * DMODEL];
__device__ __nv_bfloat16 g_up_h[NTOK * FFN];
__device__ uint8_t g_up_8h[NTOK * FFN], g_up_8l[NTOK * FFN];

__device__ __nv_bfloat16 s_emb_h[EMB_N];
__device__ uint8_t s_emb_8h[EMB_N], s_emb_8l[EMB_N];
__device__ __nv_bfloat16 s_qw_h[QW_N];
__device__ uint8_t s_qw_8h[QW_N], s_qw_8l[QW_N];
__device__ __nv_bfloat16 s_kw_h[KW_N];
__device__ uint8_t s_kw_8h[KW_N], s_kw_8l[KW_N];
__device__ __nv_bfloat16 s_vw_h[KW_N];
__device__ uint8_t s_vw_8h[KW_N], s_vw_8l[KW_N];
__device__ __nv_bfloat16 s_ow_h[QW_N];
__device__ uint8_t s_ow_8h[QW_N], s_ow_8l[QW_N];
__device__ __nv_bfloat16 s_w1_h[W1_N];
__device__ uint8_t s_w1_8h[W1_N], s_w1_8l[W1_N];
__device__ __nv_bfloat16 s_w2_h[W1_N];
__device__ uint8_t s_w2_8h[W1_N], s_w2_8l[W1_N];
__device__ __nv_bfloat16 s_w3_h[W1_N];
__device__ uint8_t s_w3_8h[W1_N], s_w3_8l[W1_N];

// ---------------- helpers ----------------
__device__ __forceinline__ void cpa16(uint32_t s, const void* g) {
    asm volatile("cp.async.cg.shared.global [%0], [%1], 16;" :: "r"(s), "l"(g));
}
__device__ __forceinline__ uint8_t to_e4m3(float x) {
    return (uint8_t)__nv_cvt_float_to_fp8(x, __NV_SATFINITE, __NV_E4M3);
}
__device__ __forceinline__ void split3(float x, float S, __nv_bfloat16& bh,
                                       uint8_t& qh, uint8_t& ql) {
    bh = __float2bfloat16(x);
    float r = x - __bfloat162float(bh);
    qh = to_e4m3(x * S);
    ql = to_e4m3(r * (S * 256.0f));
}
__device__ __forceinline__ void mma_bf16(float* d, const uint32_t* a, const uint32_t* b) {
    asm volatile(
        "mma.sync.aligned.m16n8k16.row.col.f32.bf16.bf16.f32 "
        "{%0,%1,%2,%3},{%4,%5,%6,%7},{%8,%9},{%0,%1,%2,%3};"
        : "+f"(d[0]), "+f"(d[1]), "+f"(d[2]), "+f"(d[3])
        : "r"(a[0]), "r"(a[1]), "r"(a[2]), "r"(a[3]), "r"(b[0]), "r"(b[1]));
}
__device__ __forceinline__ void mma_fp8(float* d, const uint32_t* a, const uint32_t* b) {
    asm volatile(
        "mma.sync.aligned.m16n8k32.row.col.f32.e4m3.e4m3.f32 "
        "{%0,%1,%2,%3},{%4,%5,%6,%7},{%8,%9},{%0,%1,%2,%3};"
        : "+f"(d[0]), "+f"(d[1]), "+f"(d[2]), "+f"(d[3])
        : "r"(a[0]), "r"(a[1]), "r"(a[2]), "r"(a[3]), "r"(b[0]), "r"(b[1]));
}
__device__ __forceinline__ void ldsm4(uint32_t* r, uint32_t addr) {
    asm volatile("ldmatrix.sync.aligned.m8n8.x4.shared.b16 {%0,%1,%2,%3}, [%4];"
                 : "=r"(r[0]), "=r"(r[1]), "=r"(r[2]), "=r"(r[3]) : "r"(addr));
}

// ---------------- pre-pass: fp32 weights -> bf16 hi + fp8 hi/lo planes ----------------
__global__ void split_kernel(const float* __restrict__ src,
                             __nv_bfloat16* __restrict__ hi,
                             uint8_t* __restrict__ f8h,
                             uint8_t* __restrict__ f8l) {
    int idx = blockIdx.x * 256 + threadIdx.x;   // float4 index
    float4 v = ((const float4*)src)[idx];
    float vv[4] = {v.x, v.y, v.z, v.w};
    __nv_bfloat16 bh[4];
    uchar4 qh, ql;
    uint8_t* qhp = &qh.x;
    uint8_t* qlp = &ql.x;
#pragma unroll
    for (int j = 0; j < 4; j++) split3(vv[j], SW_W, bh[j], qhp[j], qlp[j]);
    __nv_bfloat162* hp = (__nv_bfloat162*)hi;
    hp[idx * 2]     = __nv_bfloat162{bh[0], bh[1]};
    hp[idx * 2 + 1] = __nv_bfloat162{bh[2], bh[3]};
    ((uchar4*)f8h)[idx] = qh;
    ((uchar4*)f8l)[idx] = ql;
}

// ---------------- embedding gather ----------------
__global__ void embed_kernel(const int* __restrict__ ids,
                             const float* __restrict__ emb,
                             float* __restrict__ x) {
    int idx = blockIdx.x * 256 + threadIdx.x;
    int n = idx >> 8;
    int c = idx & 255;
    const float4* e4 = (const float4*)emb;
    ((float4*)x)[idx] = e4[(size_t)ids[n] * 256 + c];
}

// ---------------- RMSNorm -> planes ----------------
__global__ void rmsnorm_split_kernel(const float* __restrict__ x,
                                     const float* __restrict__ w,
                                     __nv_bfloat16* __restrict__ hi,
                                     uint8_t* __restrict__ f8h,
                                     uint8_t* __restrict__ f8l) {
    int n = blockIdx.x;
    int tid = threadIdx.x;
    const float4* xr = (const float4*)(x + (size_t)n * DMODEL);
    float4 v = xr[tid];
    float ss = v.x * v.x + v.y * v.y + v.z * v.z + v.w * v.w;
#pragma unroll
    for (int o = 16; o > 0; o >>= 1) ss += __shfl_xor_sync(0xffffffffu, ss, o);
    __shared__ float red[8];
    if ((tid & 31) == 0) red[tid >> 5] = ss;
    __syncthreads();
    float tot = 0.f;
#pragma unroll
    for (int i = 0; i < 8; i++) tot += red[i];
    float r = rsqrtf(tot * (1.0f / DMODEL) + 1e-6f);
    float4 wv = ((const float4*)w)[tid];
    float ov[4] = {wv.x * v.x * r, wv.y * v.y * r, wv.z * v.z * r, wv.w * v.w * r};
    __nv_bfloat16 bh[4];
    uchar4 qh, ql;
    uint8_t* qhp = &qh.x;
    uint8_t* qlp = &ql.x;
#pragma unroll
    for (int j = 0; j < 4; j++) split3(ov[j], SA_H, bh[j], qhp[j], qlp[j]);
    __nv_bfloat162* hp = (__nv_bfloat162*)(hi + (size_t)n * DMODEL);
    hp[tid * 2]     = __nv_bfloat162{bh[0], bh[1]};
    hp[tid * 2 + 1] = __nv_bfloat162{bh[2], bh[3]};
    ((uchar4*)(f8h + (size_t)n * DMODEL))[tid] = qh;
    ((uchar4*)(f8l + (size_t)n * DMODEL))[tid] = ql;
}

// ---------------- hybrid bf16-hi + fp8-cross GEMM ----------------
// C[N,M] = A[N,K] * W[M,K]^T; A/W as (bf16 hi, fp8 S*x, fp8 S*256*lo) planes.
// result = acc_hh + acc_cross * invc, invc = 1/(Sa*Sw*256)
// grid: (NTOK/128, M/128) token-fast. Tile 128x128, K-chunk 32, 3-stage cp.async.
// EPI: 0 store fp32, 1 +residual, 2 SiLU, 3 (acc*aux) -> output planes (scale SA_UP)
#define KC 32
#define ABH_OFF 0               // 128 rows * 80 B (32 bf16 + pad)
#define A8H_OFF 10240           // 128 rows * 48 B (32 B + pad)
#define A8L_OFF 16384
#define WBH_OFF 22528
#define W8H_OFF 32768
#define W8L_OFF 38912
#define STAGE_B 45056
#define NST 3
#define GEMM_SMEM (NST * STAGE_B)   // 135168 B

template <int EPI>
__global__ __launch_bounds__(256) void gemm_hyb(
    const __nv_bfloat16* __restrict__ Ahi, const uint8_t* __restrict__ A8h,
    const uint8_t* __restrict__ A8l,
    const __nv_bfloat16* __restrict__ Whi, const uint8_t* __restrict__ W8h,
    const uint8_t* __restrict__ W8l,
    float* __restrict__ C, const float* __restrict__ aux,
    __nv_bfloat16* __restrict__ Phi, uint8_t* __restrict__ P8h,
    uint8_t* __restrict__ P8l,
    int K, int M, float invc) {
    extern __shared__ char smraw[];
    uint32_t sbase = (uint32_t)__cvta_generic_to_shared(smraw);
    int tid = threadIdx.x, lane = tid & 31, warp = tid >> 5;
    int wm = warp >> 2, wn = warp & 3;
    int n0 = blockIdx.x * 128, m0 = blockIdx.y * 128;

    const __nv_bfloat16* Ah = Ahi + (size_t)n0 * K;
    const uint8_t* A8hg = A8h + (size_t)n0 * K;
    const uint8_t* A8lg = A8l + (size_t)n0 * K;
    const __nv_bfloat16* Wh = Whi + (size_t)m0 * K;
    const uint8_t* W8hg = W8h + (size_t)m0 * K;
    const uint8_t* W8lg = W8l + (size_t)m0 * K;

    float acch[4][4][4] = {};
    float accx[4][4][4] = {};

    auto load_stage = [&](int s, int kb) {
        uint32_t base = sbase + s * STAGE_B;
        {   // bf16 planes: 128 rows x 32 bf16 (4 granules/row)
            int row = tid >> 2, q = tid & 3;
#pragma unroll
            for (int hf = 0; hf < 2; hf++) {
                int rr = row + hf * 64;
                cpa16(base + ABH_OFF + rr * 80 + q * 16, Ah + (size_t)rr * K + kb + q * 8);
                cpa16(base + WBH_OFF + rr * 80 + q * 16, Wh + (size_t)rr * K + kb + q * 8);
            }
        }
        {   // fp8 planes: 128 rows x 32 B (2 granules/row)
            int row = tid >> 1, hb = (tid & 1) * 16;
            cpa16(base + A8H_OFF + row * 48 + hb, A8hg + (size_t)row * K + kb + hb);
            cpa16(base + A8L_OFF + row * 48 + hb, A8lg + (size_t)row * K + kb + hb);
            cpa16(base + W8H_OFF + row * 48 + hb, W8hg + (size_t)row * K + kb + hb);
            cpa16(base + W8L_OFF + row * 48 + hb, W8lg + (size_t)row * K + kb + hb);
        }
        asm volatile("cp.async.commit_group;" ::: "memory");
    };

    int KT = K >> 5;
    load_stage(0, 0);
    load_stage(1, KC);

    int arow = wm * 64 + ((lane >> 3) & 1) * 8 + (lane & 7);
    int wrow = wn * 32 + (lane >> 4) * 8 + (lane & 7);

    for (int kt = 0; kt < KT; kt++) {
        asm volatile("cp.async.wait_group 1;" ::: "memory");
        __syncthreads();
        if (kt + 2 < KT) load_stage((kt + 2) % NST, (kt + 2) * KC);
        else asm volatile("cp.async.commit_group;" ::: "memory");

        uint32_t st = sbase + (kt % NST) * STAGE_B;

        // ---- bf16 main term (K=32 via 2 x k16) ----
#pragma unroll
        for (int ks = 0; ks < 2; ks++) {
            int kcol = ks * 16;
            uint32_t ah[4][4], bh[4][2];
            uint32_t aoff = st + ABH_OFF + arow * 80 + (kcol + (lane >> 4) * 8) * 2;
#pragma unroll
            for (int i = 0; i < 4; i++) ldsm4(ah[i], aoff + i * 16 * 80);
            uint32_t woff = st + WBH_OFF + wrow * 80 + (kcol + ((lane >> 3) & 1) * 8) * 2;
            ldsm4(&bh[0][0], woff);
            ldsm4(&bh[2][0], woff + 16 * 80);
#pragma unroll
            for (int i = 0; i < 4; i++)
#pragma unroll
                for (int j = 0; j < 4; j++)
                    mma_bf16(acch[i][j], ah[i], bh[j]);
        }

        // ---- fp8 cross terms (K=32 in one k32 MMA each) ----
        {
            uint32_t a8h[4][4], a8l[4][4], b8h[4][2], b8l[4][2];
            uint32_t a8off = st + A8H_OFF + arow * 48 + (lane >> 4) * 16;
#pragma unroll
            for (int i = 0; i < 4; i++) ldsm4(a8h[i], a8off + i * 16 * 48);
            a8off = st + A8L_OFF + arow * 48 + (lane >> 4) * 16;
#pragma unroll
            for (int i = 0; i < 4; i++) ldsm4(a8l[i], a8off + i * 16 * 48);
            uint32_t b8off = st + W8H_OFF + wrow * 48 + ((lane >> 3) & 1) * 16;
            ldsm4(&b8h[0][0], b8off);
            ldsm4(&b8h[2][0], b8off + 16 * 48);
            b8off = st + W8L_OFF + wrow * 48 + ((lane >> 3) & 1) * 16;
            ldsm4(&b8l[0][0], b8off);
            ldsm4(&b8l[2][0], b8off + 16 * 48);
#pragma unroll
            for (int i = 0; i < 4; i++)
#pragma unroll
                for (int j = 0; j < 4; j++) {
                    mma_fp8(accx[i][j], a8h[i], b8l[j]);
                    mma_fp8(accx[i][j], a8l[i], b8h[j]);
                }
        }
    }

    // ---- epilogue ----
    int rr = lane >> 2, cc = (lane & 3) * 2;
#pragma unroll
    for (int i = 0; i < 4; i++) {
#pragma unroll
        for (int half = 0; half < 2; half++) {
            int grow = n0 + wm * 64 + i * 16 + rr + half * 8;
#pragma unroll
            for (int j = 0; j < 4; j++) {
                int gcol = m0 + wn * 32 + j * 8 + cc;
                size_t off = (size_t)grow * M + gcol;
                float2 v;
                v.x = acch[i][j][half * 2]     + accx[i][j][half * 2]     * invc;
                v.y = acch[i][j][half * 2 + 1] + accx[i][j][half * 2 + 1] * invc;
                if (EPI == 1) {
                    float2 rv = *(const float2*)(aux + off);
                    v.x += rv.x; v.y += rv.y;
                } else if (EPI == 2) {
                    v.x = v.x / (1.0f + __expf(-v.x));
                    v.y = v.y / (1.0f + __expf(-v.y));
                } else if (EPI == 3) {
                    float2 rv = *(const float2*)(aux + off);
                    v.x *= rv.x; v.y *= rv.y;
                    __nv_bfloat16 h0, h1;
                    uint8_t qh0, qh1, ql0, ql1;
                    split3(v.x, SA_UP, h0, qh0, ql0);
                    split3(v.y, SA_UP, h1, qh1, ql1);
                    *(__nv_bfloat162*)(Phi + off) = __nv_bfloat162{h0, h1};
                    P8h[off] = qh0; P8h[off + 1] = qh1;
                    P8l[off] = ql0; P8l[off + 1] = ql1;
                }
                if (EPI != 3) *(float2*)(C + off) = v;
            }
        }
    }
}

// ---------------- causal flash attention (fp32, GQA, fused RoPE) -> planes ----------------
__global__ __launch_bounds__(256) void attn_kernel(
    const float* __restrict__ Q, const float* __restrict__ K,
    const float* __restrict__ V,
    __nv_bfloat16* __restrict__ Ohi, uint8_t* __restrict__ O8h,
    uint8_t* __restrict__ O8l) {
    __shared__ float Qs[64][64];
    __shared__ float Ks[32][68];
    __shared__ float Vs[32][64];
    __shared__ float Ps[64][33];
    int bh = blockIdx.y;
    int b = bh >> 4;
    int h = bh & 15;
    int kvh = h >> 2;
    int q0 = blockIdx.x * 64;
    int tid = threadIdx.x;
    int lane = tid & 31, warp = tid >> 5;
    const float scale = 0.125f;

    const float* Qbase = Q + ((size_t)(b * SEQ + q0)) * DMODEL + h * HEADDIM;
    for (int i = tid; i < 64 * 8; i += 256) {
        int row = i >> 3, c4 = i & 7;
        int t = q0 + row;
        const float* qp = Qbase + (size_t)row * DMODEL;
        float4 x1 = *(const float4*)(qp + c4 * 4);
        float4 x2 = *(const float4*)(qp + c4 * 4 + 32);
        float4 o1, o2;
        float* x1p = &x1.x; float* x2p = &x2.x;
        float* o1p = &o1.x; float* o2p = &o2.x;
#pragma unroll
        for (int j = 0; j < 4; j++) {
            int d = c4 * 4 + j;
            float inv = 1.0f / powf(10000.0f, (float)d * (1.0f / 32.0f));
            float s, c;
            sincosf((float)t * inv, &s, &c);
            o1p[j] = (x1p[j] * c - x2p[j] * s) * scale;
            o2p[j] = (x2p[j] * c + x1p[j] * s) * scale;
        }
        *(float4*)&Qs[row][c4 * 4] = o1;
        *(float4*)&Qs[row][c4 * 4 + 32] = o2;
    }

    float m[8], l[8], acc0[8], acc1[8];
#pragma unroll
    for (int r = 0; r < 8; r++) { m[r] = -1e30f; l[r] = 0.f; acc0[r] = 0.f; acc1[r] = 0.f; }

    int kend = q0 + 64;
    for (int kc = 0; kc < kend; kc += 32) {
        __syncthreads();
        const float* Kbase = K + ((size_t)(b * SEQ + kc)) * KVDIM + kvh * HEADDIM;
        const float* Vbase = V + ((size_t)(b * SEQ + kc)) * KVDIM + kvh * HEADDIM;
        for (int i = tid; i < 32 * 8; i += 256) {
            int row = i >> 3, c4 = i & 7;
            int t = kc + row;
            const float* kp = Kbase + (size_t)row * KVDIM;
            float4 x1 = *(const float4*)(kp + c4 * 4);
            float4 x2 = *(const float4*)(kp + c4 * 4 + 32);
            float4 o1, o2;
            float* x1p = &x1.x; float* x2p = &x2.x;
            float* o1p = &o1.x; float* o2p = &o2.x;
#pragma unroll
            for (int j = 0; j < 4; j++) {
                int d = c4 * 4 + j;
                float inv = 1.0f / powf(10000.0f, (float)d * (1.0f / 32.0f));
                float s, c;
                sincosf((float)t * inv, &s, &c);
                o1p[j] = x1p[j] * c - x2p[j] * s;
                o2p[j] = x2p[j] * c + x1p[j] * s;
            }
            *(float4*)&Ks[row][c4 * 4] = o1;
            *(float4*)&Ks[row][c4 * 4 + 32] = o2;
        }
        for (int i = tid; i < 32 * 16; i += 256) {
            int row = i >> 4, c = (i & 15) * 4;
            float4 vv = *(const float4*)(Vbase + (size_t)row * KVDIM + c);
            *(float4*)&Vs[row][c] = vv;
        }
        __syncthreads();

        float s[8] = {0.f, 0.f, 0.f, 0.f, 0.f, 0.f, 0.f, 0.f};
#pragma unroll
        for (int d4 = 0; d4 < 16; d4++) {
            float4 kv = *(const float4*)&Ks[lane][d4 * 4];
#pragma unroll
            for (int r = 0; r < 8; r++) {
                float4 qv = *(const float4*)&Qs[warp * 8 + r][d4 * 4];
                s[r] += qv.x * kv.x + qv.y * kv.y + qv.z * kv.z + qv.w * kv.w;
            }
        }
        int key = kc + lane;
#pragma unroll
        for (int r = 0; r < 8; r++) {
            int qrow = q0 + warp * 8 + r;
            float sv = (key <= qrow) ? s[r] : -1e30f;
            float mx = sv;
#pragma unroll
            for (int o = 16; o > 0; o >>= 1) mx = fmaxf(mx, __shfl_xor_sync(0xffffffffu, mx, o));
            float mn = fmaxf(m[r], mx);
            float p = __expf(sv - mn);
            float cor = __expf(m[r] - mn);
            float ps = p;
#pragma unroll
            for (int o = 16; o > 0; o >>= 1) ps += __shfl_xor_sync(0xffffffffu, ps, o);
            l[r] = l[r] * cor + ps;
            acc0[r] *= cor;
            acc1[r] *= cor;
            m[r] = mn;
            Ps[warp * 8 + r][lane] = p;
        }
        __syncwarp();
#pragma unroll 4
        for (int j = 0; j < 32; j++) {
            float v0 = Vs[j][lane];
            float v1 = Vs[j][lane + 32];
#pragma unroll
            for (int r = 0; r < 8; r++) {
                float p = Ps[warp * 8 + r][j];
                acc0[r] += p * v0;
                acc1[r] += p * v1;
            }
        }
    }

    size_t obase = ((size_t)(b * SEQ + q0)) * DMODEL + h * HEADDIM;
#pragma unroll
    for (int r = 0; r < 8; r++) {
        int row = warp * 8 + r;
        float inv = 1.0f / l[r];
        float v0 = acc0[r] * inv, v1 = acc1[r] * inv;
        __nv_bfloat16 h0, h1;
        uint8_t qh0, ql0, qh1, ql1;
        split3(v0, SA_H, h0, qh0, ql0);
        split3(v1, SA_H, h1, qh1, ql1);
        size_t o0 = obase + (size_t)row * DMODEL + lane;
        Ohi[o0] = h0;  O8h[o0] = qh0;  O8l[o0] = ql0;
        Ohi[o0 + 32] = h1;  O8h[o0 + 32] = qh1;  O8l[o0 + 32] = ql1;
    }
}

// ---------------- host orchestration ----------------
extern "C" void kernel_launch(void* const* d_in, const int* in_sizes, int n_in,
                              void* d_out, int out_size) {
    const int*   ids = (const int*)d_in[0];
    const float* emb = (const float*)d_in[1];
    const float* ln1 = (const float*)d_in[2];
    const float* qw  = (const float*)d_in[3];
    const float* kw  = (const float*)d_in[4];
    const float* vw  = (const float*)d_in[5];
    const float* ow  = (const float*)d_in[6];
    const float* ln2 = (const float*)d_in[7];
    const float* w1  = (const float*)d_in[8];
    const float* w2  = (const float*)d_in[9];
    const float* w3  = (const float*)d_in[10];
    const float* lnf = (const float*)d_in[11];
    float* out = (float*)d_out;

    float *x, *q, *k, *v, *gate;
    __nv_bfloat16 *hh, *oh, *uph;
    uint8_t *h8h, *h8l, *o8h, *o8l, *up8h, *up8l;
    __nv_bfloat16 *embh, *qwh, *kwh, *vwh, *owh, *w1h, *w2h, *w3h;
    uint8_t *emb8h, *emb8l, *qw8h, *qw8l, *kw8h, *kw8l, *vw8h, *vw8l;
    uint8_t *ow8h, *ow8l, *w18h, *w18l, *w28h, *w28l, *w38h, *w38l;
    cudaGetSymbolAddress((void**)&x, g_x);
    cudaGetSymbolAddress((void**)&q, g_q);
    cudaGetSymbolAddress((void**)&k, g_k);
    cudaGetSymbolAddress((void**)&v, g_v);
    cudaGetSymbolAddress((void**)&gate, g_gate);
    cudaGetSymbolAddress((void**)&hh, g_h_h);
    cudaGetSymbolAddress((void**)&h8h, g_h_8h);
    cudaGetSymbolAddress((void**)&h8l, g_h_8l);
    cudaGetSymbolAddress((void**)&oh, g_o_h);
    cudaGetSymbolAddress((void**)&o8h, g_o_8h);
    cudaGetSymbolAddress((void**)&o8l, g_o_8l);
    cudaGetSymbolAddress((void**)&uph, g_up_h);
    cudaGetSymbolAddress((void**)&up8h, g_up_8h);
    cudaGetSymbolAddress((void**)&up8l, g_up_8l);
    cudaGetSymbolAddress((void**)&embh, s_emb_h);
    cudaGetSymbolAddress((void**)&emb8h, s_emb_8h);
    cudaGetSymbolAddress((void**)&emb8l, s_emb_8l);
    cudaGetSymbolAddress((void**)&qwh, s_qw_h);
    cudaGetSymbolAddress((void**)&qw8h, s_qw_8h);
    cudaGetSymbolAddress((void**)&qw8l, s_qw_8l);
    cudaGetSymbolAddress((void**)&kwh, s_kw_h);
    cudaGetSymbolAddress((void**)&kw8h, s_kw_8h);
    cudaGetSymbolAddress((void**)&kw8l, s_kw_8l);
    cudaGetSymbolAddress((void**)&vwh, s_vw_h);
    cudaGetSymbolAddress((void**)&vw8h, s_vw_8h);
    cudaGetSymbolAddress((void**)&vw8l, s_vw_8l);
    cudaGetSymbolAddress((void**)&owh, s_ow_h);
    cudaGetSymbolAddress((void**)&ow8h, s_ow_8h);
    cudaGetSymbolAddress((void**)&ow8l, s_ow_8l);
    cudaGetSymbolAddress((void**)&w1h, s_w1_h);
    cudaGetSymbolAddress((void**)&w18h, s_w1_8h);
    cudaGetSymbolAddress((void**)&w18l, s_w1_8l);
    cudaGetSymbolAddress((void**)&w2h, s_w2_h);
    cudaGetSymbolAddress((void**)&w28h, s_w2_8h);
    cudaGetSymbolAddress((void**)&w28l, s_w2_8l);
    cudaGetSymbolAddress((void**)&w3h, s_w3_h);
    cudaGetSymbolAddress((void**)&w38h, s_w3_8h);
    cudaGetSymbolAddress((void**)&w38l, s_w3_8l);

    cudaFuncSetAttribute(gemm_hyb<0>, cudaFuncAttributeMaxDynamicSharedMemorySize, GEMM_SMEM);
    cudaFuncSetAttribute(gemm_hyb<1>, cudaFuncAttributeMaxDynamicSharedMemorySize, GEMM_SMEM);
    cudaFuncSetAttribute(gemm_hyb<2>, cudaFuncAttributeMaxDynamicSharedMemorySize, GEMM_SMEM);
    cudaFuncSetAttribute(gemm_hyb<3>, cudaFuncAttributeMaxDynamicSharedMemorySize, GEMM_SMEM);

    const float invc16 = 1.0f / (SA_H * SW_W * 256.0f);
    const float invc32 = 1.0f / (SA_UP * SW_W * 256.0f);

    // pre-pass: split weights into bf16-hi + fp8 planes
    split_kernel<<<EMB_N / 1024, 256>>>(emb, embh, emb8h, emb8l);
    split_kernel<<<QW_N / 1024, 256>>>(qw, qwh, qw8h, qw8l);
    split_kernel<<<KW_N / 1024, 256>>>(kw, kwh, kw8h, kw8l);
    split_kernel<<<KW_N / 1024, 256>>>(vw, vwh, vw8h, vw8l);
    split_kernel<<<QW_N / 1024, 256>>>(ow, owh, ow8h, ow8l);
    split_kernel<<<W1_N / 1024, 256>>>(w1, w1h, w18h, w18l);
    split_kernel<<<W1_N / 1024, 256>>>(w2, w2h, w28h, w28l);
    split_kernel<<<W1_N / 1024, 256>>>(w3, w3h, w38h, w38l);

    embed_kernel<<<NTOK, 256>>>(ids, emb, x);

    const int TB = NTOK / 128;   // token blocks (fast grid dim for weight L2 reuse)
    for (int l = 0; l < NLAYER; l++) {
        size_t qo = (size_t)l * DMODEL * DMODEL;
        size_t ko = (size_t)l * KVDIM * DMODEL;
        size_t fo = (size_t)l * FFN * DMODEL;

        rmsnorm_split_kernel<<<NTOK, 256>>>(x, ln1 + l * DMODEL, hh, h8h, h8l);
        gemm_hyb<0><<<dim3(TB, DMODEL / 128), 256, GEMM_SMEM>>>(
            hh, h8h, h8l, qwh + qo, qw8h + qo, qw8l + qo,
            q, nullptr, nullptr, nullptr, nullptr, DMODEL, DMODEL, invc16);
        gemm_hyb<0><<<dim3(TB, KVDIM / 128), 256, GEMM_SMEM>>>(
            hh, h8h, h8l, kwh + ko, kw8h + ko, kw8l + ko,
            k, nullptr, nullptr, nullptr, nullptr, DMODEL, KVDIM, invc16);
        gemm_hyb<0><<<dim3(TB, KVDIM / 128), 256, GEMM_SMEM>>>(
            hh, h8h, h8l, vwh + ko, vw8h + ko, vw8l + ko,
            v, nullptr, nullptr, nullptr, nullptr, DMODEL, KVDIM, invc16);
        attn_kernel<<<dim3(SEQ / 64, 2 * NHEAD), 256>>>(q, k, v, oh, o8h, o8l);
        gemm_hyb<1><<<dim3(TB, DMODEL / 128), 256, GEMM_SMEM>>>(
            oh, o8h, o8l, owh + qo, ow8h + qo, ow8l + qo,
            x, x, nullptr, nullptr, nullptr, DMODEL, DMODEL, invc16);
        rmsnorm_split_kernel<<<NTOK, 256>>>(x, ln2 + l * DMODEL, hh, h8h, h8l);
        gemm_hyb<2><<<dim3(TB, FFN / 128), 256, GEMM_SMEM>>>(
            hh, h8h, h8l, w1h + fo, w18h + fo, w18l + fo,
            gate, nullptr, nullptr, nullptr, nullptr, DMODEL, FFN, invc16);
        gemm_hyb<3><<<dim3(TB, FFN / 128), 256, GEMM_SMEM>>>(
            hh, h8h, h8l, w3h + fo, w38h + fo, w38l + fo,
            nullptr, gate, uph, up8h, up8l, DMODEL, FFN, invc16);
        gemm_hyb<1><<<dim3(TB, DMODEL / 128), 256, GEMM_SMEM>>>(
            uph, up8h, up8l, w2h + fo, w28h + fo, w28l + fo,
            x, x, nullptr, nullptr, nullptr, FFN, DMODEL, invc32);
    }

    rmsnorm_split_kernel<<<NTOK, 256>>>(x, lnf, hh, h8h, h8l);
    gemm_hyb<0><<<dim3(TB, VOCAB / 128), 256, GEMM_SMEM>>>(
        hh, h8h, h8l, embh, emb8h, emb8l,
        out, nullptr, nullptr, nullptr, nullptr, DMODEL, VOCAB, invc16);
}

// round 8
// speedup vs baseline: 1.3002x; 1.3002x over previous
#include <cuda_runtime.h>
#include <cuda_bf16.h>
#include <stdint.h>
#include <math.h>

#define NTOK 2048
#define DMODEL 1024
#define NHEAD 16
#define NKV 4
#define HEADDIM 64
#define FFN 4096
#define VOCAB 32000
#define NLAYER 4
#define SEQ 1024
#define KVDIM (NKV * HEADDIM)   // 256

#define EMB_N (VOCAB * DMODEL)
#define QW_N (NLAYER * DMODEL * DMODEL)
#define KW_N (NLAYER * KVDIM * DMODEL)
#define W1_N (NLAYER * FFN * DMODEL)

// ---------------- scratch (device globals; no runtime allocation) ----------------
__device__ float g_x[NTOK * DMODEL];
__device__ float g_q[NTOK * DMODEL];
__device__ float g_k[NTOK * KVDIM];
__device__ float g_v[NTOK * KVDIM];
__device__ float g_gate[NTOK * FFN];

__device__ __nv_bfloat16 g_h_h[NTOK * DMODEL], g_h_l[NTOK * DMODEL];
__device__ __nv_bfloat16 g_o_h[NTOK * DMODEL], g_o_l[NTOK * DMODEL];
__device__ __nv_bfloat16 g_up_h[NTOK * FFN],  g_up_l[NTOK * FFN];

__device__ __nv_bfloat16 s_emb_h[EMB_N], s_emb_l[EMB_N];
__device__ __nv_bfloat16 s_qw_h[QW_N],  s_qw_l[QW_N];
__device__ __nv_bfloat16 s_kw_h[KW_N],  s_kw_l[KW_N];
__device__ __nv_bfloat16 s_vw_h[KW_N],  s_vw_l[KW_N];
__device__ __nv_bfloat16 s_ow_h[QW_N],  s_ow_l[QW_N];
__device__ __nv_bfloat16 s_w1_h[W1_N],  s_w1_l[W1_N];
__device__ __nv_bfloat16 s_w2_h[W1_N],  s_w2_l[W1_N];
__device__ __nv_bfloat16 s_w3_h[W1_N],  s_w3_l[W1_N];

// ---------------- helpers ----------------
__device__ __forceinline__ void cpa16(uint32_t s, const void* g) {
    asm volatile("cp.async.cg.shared.global [%0], [%1], 16;" :: "r"(s), "l"(g));
}
__device__ __forceinline__ void split2(float x, __nv_bfloat16& h, __nv_bfloat16& l) {
    h = __float2bfloat16(x);
    l = __float2bfloat16(x - __bfloat162float(h));
}
__device__ __forceinline__ void mma_bf16(float* d, const uint32_t* a, const uint32_t* b) {
    asm volatile(
        "mma.sync.aligned.m16n8k16.row.col.f32.bf16.bf16.f32 "
        "{%0,%1,%2,%3},{%4,%5,%6,%7},{%8,%9},{%0,%1,%2,%3};"
        : "+f"(d[0]), "+f"(d[1]), "+f"(d[2]), "+f"(d[3])
        : "r"(a[0]), "r"(a[1]), "r"(a[2]), "r"(a[3]), "r"(b[0]), "r"(b[1]));
}

// ---------------- pre-pass: fp32 -> bf16 hi/lo planes ----------------
__global__ void split_kernel(const float* __restrict__ src,
                             __nv_bfloat16* __restrict__ hi,
                             __nv_bfloat16* __restrict__ lo) {
    int idx = blockIdx.x * 256 + threadIdx.x;   // float4 index
    float4 v = ((const float4*)src)[idx];
    __nv_bfloat16 h0, h1, h2, h3, l0, l1, l2, l3;
    split2(v.x, h0, l0);
    split2(v.y, h1, l1);
    split2(v.z, h2, l2);
    split2(v.w, h3, l3);
    __nv_bfloat162* hp = (__nv_bfloat162*)hi;
    __nv_bfloat162* lp = (__nv_bfloat162*)lo;
    hp[idx * 2]     = __nv_bfloat162{h0, h1};
    hp[idx * 2 + 1] = __nv_bfloat162{h2, h3};
    lp[idx * 2]     = __nv_bfloat162{l0, l1};
    lp[idx * 2 + 1] = __nv_bfloat162{l2, l3};
}

// ---------------- embedding gather ----------------
__global__ void embed_kernel(const int* __restrict__ ids,
                             const float* __restrict__ emb,
                             float* __restrict__ x) {
    int idx = blockIdx.x * 256 + threadIdx.x;
    int n = idx >> 8;
    int c = idx & 255;
    const float4* e4 = (const float4*)emb;
    ((float4*)x)[idx] = e4[(size_t)ids[n] * 256 + c];
}

// ---------------- RMSNorm -> bf16 hi/lo planes ----------------
__global__ void rmsnorm_split_kernel(const float* __restrict__ x,
                                     const float* __restrict__ w,
                                     __nv_bfloat16* __restrict__ hi,
                                     __nv_bfloat16* __restrict__ lo) {
    int n = blockIdx.x;
    int tid = threadIdx.x;
    const float4* xr = (const float4*)(x + (size_t)n * DMODEL);
    float4 v = xr[tid];
    float ss = v.x * v.x + v.y * v.y + v.z * v.z + v.w * v.w;
#pragma unroll
    for (int o = 16; o > 0; o >>= 1) ss += __shfl_xor_sync(0xffffffffu, ss, o);
    __shared__ float red[8];
    if ((tid & 31) == 0) red[tid >> 5] = ss;
    __syncthreads();
    float tot = 0.f;
#pragma unroll
    for (int i = 0; i < 8; i++) tot += red[i];
    float r = rsqrtf(tot * (1.0f / DMODEL) + 1e-6f);
    float4 wv = ((const float4*)w)[tid];
    float o0 = wv.x * v.x * r, o1 = wv.y * v.y * r, o2 = wv.z * v.z * r, o3 = wv.w * v.w * r;
    __nv_bfloat16 h0, h1, h2, h3, l0, l1, l2, l3;
    split2(o0, h0, l0); split2(o1, h1, l1); split2(o2, h2, l2); split2(o3, h3, l3);
    __nv_bfloat162* hp = (__nv_bfloat162*)(hi + (size_t)n * DMODEL);
    __nv_bfloat162* lp = (__nv_bfloat162*)(lo + (size_t)n * DMODEL);
    hp[tid * 2]     = __nv_bfloat162{h0, h1};
    hp[tid * 2 + 1] = __nv_bfloat162{h2, h3};
    lp[tid * 2]     = __nv_bfloat162{l0, l1};
    lp[tid * 2 + 1] = __nv_bfloat162{l2, l3};
}

// ---------------- 3xBF16 tensor-core GEMM core (R4 structure, 2-stage, 82KB) ----------------
// C[N,M] = A[N,K] * W[M,K]^T, A/W as bf16 hi/lo planes.
// EPI: 0 store fp32, 1 residual add, 2 SiLU, 3 (acc*aux) -> split planes Phi/Plo
#define BK 32
#define SP 40                 // bf16 per smem row (32 data + 8 pad)
#define SP32 20               // in b32 units
#define PLANE (128 * SP)      // 5120 bf16
#define STAGE (4 * PLANE)     // 20480 bf16 per stage
#define GEMM_SMEM (2 * STAGE * 2)  // 81920 bytes -> 2 CTA/SM

template <int EPI>
__device__ __forceinline__ void gemm_core(
    __nv_bfloat16* smb,
    const __nv_bfloat16* __restrict__ Ahi, const __nv_bfloat16* __restrict__ Alo,
    const __nv_bfloat16* __restrict__ Whi, const __nv_bfloat16* __restrict__ Wlo,
    float* __restrict__ C, const float* __restrict__ aux,
    __nv_bfloat16* __restrict__ Phi, __nv_bfloat16* __restrict__ Plo,
    int K, int M, int n0, int m0) {
    int tid = threadIdx.x, lane = tid & 31, warp = tid >> 5;
    int wm = warp >> 2, wn = warp & 3;

    const __nv_bfloat16* Ah = Ahi + (size_t)n0 * K;
    const __nv_bfloat16* Al = Alo + (size_t)n0 * K;
    const __nv_bfloat16* Wh = Whi + (size_t)m0 * K;
    const __nv_bfloat16* Wl = Wlo + (size_t)m0 * K;

    float acc[4][4][4] = {};

    auto load_stage = [&](int s, int kt) {
        __nv_bfloat16* base = smb + s * STAGE;
        const __nv_bfloat16* gp[4] = {Ah + kt, Al + kt, Wh + kt, Wl + kt};
#pragma unroll
        for (int pl = 0; pl < 4; pl++) {
#pragma unroll
            for (int hf = 0; hf < 2; hf++) {
                int row = hf * 64 + (tid >> 2);
                int seg = tid & 3;
                cpa16((uint32_t)__cvta_generic_to_shared(base + pl * PLANE + row * SP + seg * 8),
                      gp[pl] + (size_t)row * K + seg * 8);
            }
        }
        asm volatile("cp.async.commit_group;" ::: "memory");
    };

    load_stage(0, 0);
    int KT = K >> 5;
    int r = lane >> 2, c = lane & 3;
    for (int kt = 0; kt < KT; kt++) {
        asm volatile("cp.async.wait_group 0;" ::: "memory");
        __syncthreads();
        if (kt + 1 < KT) load_stage((kt + 1) & 1, (kt + 1) * BK);
        const __nv_bfloat16* cb = smb + (kt & 1) * STAGE;
        const uint32_t* aH = (const uint32_t*)(cb);
        const uint32_t* aL = (const uint32_t*)(cb + PLANE);
        const uint32_t* wH = (const uint32_t*)(cb + 2 * PLANE);
        const uint32_t* wL = (const uint32_t*)(cb + 3 * PLANE);
#pragma unroll
        for (int ks = 0; ks < 2; ks++) {
            int kb = ks * 8 + c;
            uint32_t ah[4][4], bh[4][2], bl[4][2];
#pragma unroll
            for (int i = 0; i < 4; i++) {
                int m = wm * 64 + i * 16 + r;
                ah[i][0] = aH[m * SP32 + kb];
                ah[i][1] = aH[(m + 8) * SP32 + kb];
                ah[i][2] = aH[m * SP32 + kb + 4];
                ah[i][3] = aH[(m + 8) * SP32 + kb + 4];
            }
#pragma unroll
            for (int j = 0; j < 4; j++) {
                int n = wn * 32 + j * 8 + r;
                bh[j][0] = wH[n * SP32 + kb];
                bh[j][1] = wH[n * SP32 + kb + 4];
                bl[j][0] = wL[n * SP32 + kb];
                bl[j][1] = wL[n * SP32 + kb + 4];
            }
#pragma unroll
            for (int i = 0; i < 4; i++)
#pragma unroll
                for (int j = 0; j < 4; j++) {
                    mma_bf16(acc[i][j], ah[i], bh[j]);
                    mma_bf16(acc[i][j], ah[i], bl[j]);
                }
            uint32_t al[4][4];
#pragma unroll
            for (int i = 0; i < 4; i++) {
                int m = wm * 64 + i * 16 + r;
                al[i][0] = aL[m * SP32 + kb];
                al[i][1] = aL[(m + 8) * SP32 + kb];
                al[i][2] = aL[m * SP32 + kb + 4];
                al[i][3] = aL[(m + 8) * SP32 + kb + 4];
            }
#pragma unroll
            for (int i = 0; i < 4; i++)
#pragma unroll
                for (int j = 0; j < 4; j++)
                    mma_bf16(acc[i][j], al[i], bh[j]);
        }
        __syncthreads();
    }

    // epilogue
    int rr = lane >> 2, cc = (lane & 3) * 2;
#pragma unroll
    for (int i = 0; i < 4; i++) {
#pragma unroll
        for (int half = 0; half < 2; half++) {
            int grow = n0 + wm * 64 + i * 16 + rr + half * 8;
#pragma unroll
            for (int j = 0; j < 4; j++) {
                int gcol = m0 + wn * 32 + j * 8 + cc;
                size_t off = (size_t)grow * M + gcol;
                float2 v = make_float2(acc[i][j][half * 2], acc[i][j][half * 2 + 1]);
                if (EPI == 1) {
                    float2 rv = *(const float2*)(aux + off);
                    v.x += rv.x; v.y += rv.y;
                } else if (EPI == 2) {
                    v.x = v.x / (1.0f + __expf(-v.x));
                    v.y = v.y / (1.0f + __expf(-v.y));
                } else if (EPI == 3) {
                    float2 rv = *(const float2*)(aux + off);
                    v.x *= rv.x; v.y *= rv.y;
                    __nv_bfloat16 h0, h1, l0, l1;
                    split2(v.x, h0, l0);
                    split2(v.y, h1, l1);
                    *(__nv_bfloat162*)(Phi + off) = __nv_bfloat162{h0, h1};
                    *(__nv_bfloat162*)(Plo + off) = __nv_bfloat162{l0, l1};
                }
                if (EPI != 3) *(float2*)(C + off) = v;
            }
        }
    }
}

// Standard GEMM: grid (NTOK/128 fast, M/128)
template <int EPI>
__global__ __launch_bounds__(256) void gemm_bf3(
    const __nv_bfloat16* __restrict__ Ahi, const __nv_bfloat16* __restrict__ Alo,
    const __nv_bfloat16* __restrict__ Whi, const __nv_bfloat16* __restrict__ Wlo,
    float* __restrict__ C, const float* __restrict__ aux,
    __nv_bfloat16* __restrict__ Phi, __nv_bfloat16* __restrict__ Plo,
    int K, int M) {
    extern __shared__ __nv_bfloat16 smb[];
    gemm_core<EPI>(smb, Ahi, Alo, Whi, Wlo, C, aux, Phi, Plo, K, M,
                   blockIdx.x * 128, blockIdx.y * 128);
}

// Fused QKV GEMM: grid (16, 12): y<8 -> Q, y in {8,9} -> K, y in {10,11} -> V
__global__ __launch_bounds__(256) void gemm_qkv(
    const __nv_bfloat16* __restrict__ Ahi, const __nv_bfloat16* __restrict__ Alo,
    const __nv_bfloat16* __restrict__ Qwh, const __nv_bfloat16* __restrict__ Qwl,
    const __nv_bfloat16* __restrict__ Kwh, const __nv_bfloat16* __restrict__ Kwl,
    const __nv_bfloat16* __restrict__ Vwh, const __nv_bfloat16* __restrict__ Vwl,
    float* __restrict__ Cq, float* __restrict__ Ck, float* __restrict__ Cv) {
    extern __shared__ __nv_bfloat16 smb[];
    int y = blockIdx.y;
    const __nv_bfloat16 *wh, *wl;
    float* C;
    int m0, M;
    if (y < 8)       { wh = Qwh; wl = Qwl; C = Cq; m0 = y * 128;        M = DMODEL; }
    else if (y < 10) { wh = Kwh; wl = Kwl; C = Ck; m0 = (y - 8) * 128;  M = KVDIM; }
    else             { wh = Vwh; wl = Vwl; C = Cv; m0 = (y - 10) * 128; M = KVDIM; }
    gemm_core<0>(smb, Ahi, Alo, wh, wl, C, nullptr, nullptr, nullptr, DMODEL, M,
                 blockIdx.x * 128, m0);
}

// ---------------- causal flash attention (fp32, GQA, fused RoPE) ----------------
__global__ __launch_bounds__(256) void attn_kernel(
    const float* __restrict__ Q, const float* __restrict__ K,
    const float* __restrict__ V,
    __nv_bfloat16* __restrict__ Ohi, __nv_bfloat16* __restrict__ Olo) {
    __shared__ float Qs[64][64];
    __shared__ float Ks[32][68];
    __shared__ float Vs[32][64];
    __shared__ float Ps[64][33];
    int bh = blockIdx.y;
    int b = bh >> 4;
    int h = bh & 15;
    int kvh = h >> 2;
    int q0 = blockIdx.x * 64;
    int tid = threadIdx.x;
    int lane = tid & 31, warp = tid >> 5;
    const float scale = 0.125f;

    const float* Qbase = Q + ((size_t)(b * SEQ + q0)) * DMODEL + h * HEADDIM;
    for (int i = tid; i < 64 * 8; i += 256) {
        int row = i >> 3, c4 = i & 7;
        int t = q0 + row;
        const float* qp = Qbase + (size_t)row * DMODEL;
        float4 x1 = *(const float4*)(qp + c4 * 4);
        float4 x2 = *(const float4*)(qp + c4 * 4 + 32);
        float4 o1, o2;
        float* x1p = &x1.x; float* x2p = &x2.x;
        float* o1p = &o1.x; float* o2p = &o2.x;
#pragma unroll
        for (int j = 0; j < 4; j++) {
            int d = c4 * 4 + j;
            float inv = 1.0f / powf(10000.0f, (float)d * (1.0f / 32.0f));
            float s, c;
            sincosf((float)t * inv, &s, &c);
            o1p[j] = (x1p[j] * c - x2p[j] * s) * scale;
            o2p[j] = (x2p[j] * c + x1p[j] * s) * scale;
        }
        *(float4*)&Qs[row][c4 * 4] = o1;
        *(float4*)&Qs[row][c4 * 4 + 32] = o2;
    }

    float m[8], l[8], acc0[8], acc1[8];
#pragma unroll
    for (int r = 0; r < 8; r++) { m[r] = -1e30f; l[r] = 0.f; acc0[r] = 0.f; acc1[r] = 0.f; }

    int kend = q0 + 64;
    for (int kc = 0; kc < kend; kc += 32) {
        __syncthreads();
        const float* Kbase = K + ((size_t)(b * SEQ + kc)) * KVDIM + kvh * HEADDIM;
        const float* Vbase = V + ((size_t)(b * SEQ + kc)) * KVDIM + kvh * HEADDIM;
        for (int i = tid; i < 32 * 8; i += 256) {
            int row = i >> 3, c4 = i & 7;
            int t = kc + row;
            const float* kp = Kbase + (size_t)row * KVDIM;
            float4 x1 = *(const float4*)(kp + c4 * 4);
            float4 x2 = *(const float4*)(kp + c4 * 4 + 32);
            float4 o1, o2;
            float* x1p = &x1.x; float* x2p = &x2.x;
            float* o1p = &o1.x; float* o2p = &o2.x;
#pragma unroll
            for (int j = 0; j < 4; j++) {
                int d = c4 * 4 + j;
                float inv = 1.0f / powf(10000.0f, (float)d * (1.0f / 32.0f));
                float s, c;
                sincosf((float)t * inv, &s, &c);
                o1p[j] = x1p[j] * c - x2p[j] * s;
                o2p[j] = x2p[j] * c + x1p[j] * s;
            }
            *(float4*)&Ks[row][c4 * 4] = o1;
            *(float4*)&Ks[row][c4 * 4 + 32] = o2;
        }
        for (int i = tid; i < 32 * 16; i += 256) {
            int row = i >> 4, c = (i & 15) * 4;
            float4 vv = *(const float4*)(Vbase + (size_t)row * KVDIM + c);
            *(float4*)&Vs[row][c] = vv;
        }
        __syncthreads();

        float s[8] = {0.f, 0.f, 0.f, 0.f, 0.f, 0.f, 0.f, 0.f};
#pragma unroll
        for (int d4 = 0; d4 < 16; d4++) {
            float4 kv = *(const float4*)&Ks[lane][d4 * 4];
#pragma unroll
            for (int r = 0; r < 8; r++) {
                float4 qv = *(const float4*)&Qs[warp * 8 + r][d4 * 4];
                s[r] += qv.x * kv.x + qv.y * kv.y + qv.z * kv.z + qv.w * kv.w;
            }
        }
        int key = kc + lane;
#pragma unroll
        for (int r = 0; r < 8; r++) {
            int qrow = q0 + warp * 8 + r;
            float sv = (key <= qrow) ? s[r] : -1e30f;
            float mx = sv;
#pragma unroll
            for (int o = 16; o > 0; o >>= 1) mx = fmaxf(mx, __shfl_xor_sync(0xffffffffu, mx, o));
            float mn = fmaxf(m[r], mx);
            float p = __expf(sv - mn);
            float cor = __expf(m[r] - mn);
            float ps = p;
#pragma unroll
            for (int o = 16; o > 0; o >>= 1) ps += __shfl_xor_sync(0xffffffffu, ps, o);
            l[r] = l[r] * cor + ps;
            acc0[r] *= cor;
            acc1[r] *= cor;
            m[r] = mn;
            Ps[warp * 8 + r][lane] = p;
        }
        __syncwarp();
#pragma unroll 4
        for (int j = 0; j < 32; j++) {
            float v0 = Vs[j][lane];
            float v1 = Vs[j][lane + 32];
#pragma unroll
            for (int r = 0; r < 8; r++) {
                float p = Ps[warp * 8 + r][j];
                acc0[r] += p * v0;
                acc1[r] += p * v1;
            }
        }
    }

    size_t obase = ((size_t)(b * SEQ + q0)) * DMODEL + h * HEADDIM;
#pragma unroll
    for (int r = 0; r < 8; r++) {
        int row = warp * 8 + r;
        float inv = 1.0f / l[r];
        float v0 = acc0[r] * inv, v1 = acc1[r] * inv;
        __nv_bfloat16 h0, h1, l0, l1;
        split2(v0, h0, l0);
        split2(v1, h1, l1);
        size_t o0 = obase + (size_t)row * DMODEL + lane;
        Ohi[o0] = h0;  Olo[o0] = l0;
        Ohi[o0 + 32] = h1;  Olo[o0 + 32] = l1;
    }
}

// ---------------- host orchestration ----------------
extern "C" void kernel_launch(void* const* d_in, const int* in_sizes, int n_in,
                              void* d_out, int out_size) {
    const int*   ids = (const int*)d_in[0];
    const float* emb = (const float*)d_in[1];
    const float* ln1 = (const float*)d_in[2];
    const float* qw  = (const float*)d_in[3];
    const float* kw  = (const float*)d_in[4];
    const float* vw  = (const float*)d_in[5];
    const float* ow  = (const float*)d_in[6];
    const float* ln2 = (const float*)d_in[7];
    const float* w1  = (const float*)d_in[8];
    const float* w2  = (const float*)d_in[9];
    const float* w3  = (const float*)d_in[10];
    const float* lnf = (const float*)d_in[11];
    float* out = (float*)d_out;

    float *x, *q, *k, *v, *gate;
    __nv_bfloat16 *hh, *hl, *oh, *ol, *uph, *upl;
    __nv_bfloat16 *embh, *embl, *qwh, *qwl, *kwh, *kwl, *vwh, *vwl, *owh, *owl;
    __nv_bfloat16 *w1h, *w1l, *w2h, *w2l, *w3h, *w3l;
    cudaGetSymbolAddress((void**)&x, g_x);
    cudaGetSymbolAddress((void**)&q, g_q);
    cudaGetSymbolAddress((void**)&k, g_k);
    cudaGetSymbolAddress((void**)&v, g_v);
    cudaGetSymbolAddress((void**)&gate, g_gate);
    cudaGetSymbolAddress((void**)&hh, g_h_h);
    cudaGetSymbolAddress((void**)&hl, g_h_l);
    cudaGetSymbolAddress((void**)&oh, g_o_h);
    cudaGetSymbolAddress((void**)&ol, g_o_l);
    cudaGetSymbolAddress((void**)&uph, g_up_h);
    cudaGetSymbolAddress((void**)&upl, g_up_l);
    cudaGetSymbolAddress((void**)&embh, s_emb_h);
    cudaGetSymbolAddress((void**)&embl, s_emb_l);
    cudaGetSymbolAddress((void**)&qwh, s_qw_h);
    cudaGetSymbolAddress((void**)&qwl, s_qw_l);
    cudaGetSymbolAddress((void**)&kwh, s_kw_h);
    cudaGetSymbolAddress((void**)&kwl, s_kw_l);
    cudaGetSymbolAddress((void**)&vwh, s_vw_h);
    cudaGetSymbolAddress((void**)&vwl, s_vw_l);
    cudaGetSymbolAddress((void**)&owh, s_ow_h);
    cudaGetSymbolAddress((void**)&owl, s_ow_l);
    cudaGetSymbolAddress((void**)&w1h, s_w1_h);
    cudaGetSymbolAddress((void**)&w1l, s_w1_l);
    cudaGetSymbolAddress((void**)&w2h, s_w2_h);
    cudaGetSymbolAddress((void**)&w2l, s_w2_l);
    cudaGetSymbolAddress((void**)&w3h, s_w3_h);
    cudaGetSymbolAddress((void**)&w3l, s_w3_l);

    cudaFuncSetAttribute(gemm_bf3<0>, cudaFuncAttributeMaxDynamicSharedMemorySize, GEMM_SMEM);
    cudaFuncSetAttribute(gemm_bf3<1>, cudaFuncAttributeMaxDynamicSharedMemorySize, GEMM_SMEM);
    cudaFuncSetAttribute(gemm_bf3<2>, cudaFuncAttributeMaxDynamicSharedMemorySize, GEMM_SMEM);
    cudaFuncSetAttribute(gemm_bf3<3>, cudaFuncAttributeMaxDynamicSharedMemorySize, GEMM_SMEM);
    cudaFuncSetAttribute(gemm_qkv,    cudaFuncAttributeMaxDynamicSharedMemorySize, GEMM_SMEM);

    // pre-pass: split weights into bf16 hi/lo planes
    split_kernel<<<EMB_N / 1024, 256>>>(emb, embh, embl);
    split_kernel<<<QW_N / 1024, 256>>>(qw, qwh, qwl);
    split_kernel<<<KW_N / 1024, 256>>>(kw, kwh, kwl);
    split_kernel<<<KW_N / 1024, 256>>>(vw, vwh, vwl);
    split_kernel<<<QW_N / 1024, 256>>>(ow, owh, owl);
    split_kernel<<<W1_N / 1024, 256>>>(w1, w1h, w1l);
    split_kernel<<<W1_N / 1024, 256>>>(w2, w2h, w2l);
    split_kernel<<<W1_N / 1024, 256>>>(w3, w3h, w3l);

    embed_kernel<<<NTOK, 256>>>(ids, emb, x);

    const int TB = NTOK / 128;   // 16 token blocks: FAST grid dim (weight L2 reuse)
    for (int l = 0; l < NLAYER; l++) {
        size_t qo = (size_t)l * DMODEL * DMODEL;
        size_t ko = (size_t)l * KVDIM * DMODEL;
        size_t fo = (size_t)l * FFN * DMODEL;

        rmsnorm_split_kernel<<<NTOK, 256>>>(x, ln1 + l * DMODEL, hh, hl);
        gemm_qkv<<<dim3(TB, 12), 256, GEMM_SMEM>>>(
            hh, hl, qwh + qo, qwl + qo, kwh + ko, kwl + ko, vwh + ko, vwl + ko,
            q, k, v);
        attn_kernel<<<dim3(SEQ / 64, 2 * NHEAD), 256>>>(q, k, v, oh, ol);
        gemm_bf3<1><<<dim3(TB, DMODEL / 128), 256, GEMM_SMEM>>>(
            oh, ol, owh + qo, owl + qo, x, x, nullptr, nullptr, DMODEL, DMODEL);
        rmsnorm_split_kernel<<<NTOK, 256>>>(x, ln2 + l * DMODEL, hh, hl);
        gemm_bf3<2><<<dim3(TB, FFN / 128), 256, GEMM_SMEM>>>(
            hh, hl, w1h + fo, w1l + fo, gate, nullptr, nullptr, nullptr, DMODEL, FFN);
        gemm_bf3<3><<<dim3(TB, FFN / 128), 256, GEMM_SMEM>>>(
            hh, hl, w3h + fo, w3l + fo, nullptr, gate, uph, upl, DMODEL, FFN);
        gemm_bf3<1><<<dim3(TB, DMODEL / 128), 256, GEMM_SMEM>>>(
            uph, upl, w2h + fo, w2l + fo, x, x, nullptr, nullptr, FFN, DMODEL);
    }

    rmsnorm_split_kernel<<<NTOK, 256>>>(x, lnf, hh, hl);
    gemm_bf3<0><<<dim3(TB, VOCAB / 128), 256, GEMM_SMEM>>>(
        hh, hl, embh, embl, out, nullptr, nullptr, nullptr, DMODEL, VOCAB);
}

// round 9
// speedup vs baseline: 1.6350x; 1.2576x over previous
#include <cuda_runtime.h>
#include <cuda_bf16.h>
#include <cuda_fp16.h>
#include <stdint.h>
#include <math.h>

#define NTOK 2048
#define DMODEL 1024
#define NHEAD 16
#define NKV 4
#define HEADDIM 64
#define FFN 4096
#define VOCAB 32000
#define NLAYER 4
#define SEQ 1024
#define KVDIM (NKV * HEADDIM)   // 256

#define EMB_N (VOCAB * DMODEL)
#define QW_N (NLAYER * DMODEL * DMODEL)
#define KW_N (NLAYER * KVDIM * DMODEL)
#define W1_N (NLAYER * FFN * DMODEL)

// ---------------- scratch (device globals; no runtime allocation) ----------------
__device__ float g_x[NTOK * DMODEL];
__device__ float g_q[NTOK * DMODEL];
__device__ float g_k[NTOK * KVDIM];
__device__ float g_v[NTOK * KVDIM];
__device__ float g_gate[NTOK * FFN];

__device__ __half g_h_h[NTOK * DMODEL], g_h_l[NTOK * DMODEL];
__device__ __half g_o_h[NTOK * DMODEL], g_o_l[NTOK * DMODEL];
__device__ __half g_up_h[NTOK * FFN],  g_up_l[NTOK * FFN];

__device__ __half s_emb_w[EMB_N];
__device__ __half s_qw_w[QW_N];
__device__ __half s_kw_w[KW_N];
__device__ __half s_vw_w[KW_N];
__device__ __half s_ow_w[QW_N];
__device__ __half s_w1_w[W1_N];
__device__ __half s_w2_w[W1_N];
__device__ __half s_w3_w[W1_N];

// ---------------- helpers ----------------
__device__ __forceinline__ void cpa16(uint32_t s, const void* g) {
    asm volatile("cp.async.cg.shared.global [%0], [%1], 16;" :: "r"(s), "l"(g));
}
__device__ __forceinline__ void hsplit(float x, __half& h, __half& l) {
    h = __float2half_rn(x);
    l = __float2half_rn(x - __half2float(h));
}
__device__ __forceinline__ void mma_f16(float* d, const uint32_t* a, const uint32_t* b) {
    asm volatile(
        "mma.sync.aligned.m16n8k16.row.col.f32.f16.f16.f32 "
        "{%0,%1,%2,%3},{%4,%5,%6,%7},{%8,%9},{%0,%1,%2,%3};"
        : "+f"(d[0]), "+f"(d[1]), "+f"(d[2]), "+f"(d[3])
        : "r"(a[0]), "r"(a[1]), "r"(a[2]), "r"(a[3]), "r"(b[0]), "r"(b[1]));
}

// ---------------- pre-pass: fp32 weights -> single f16 plane ----------------
__global__ void split_w_kernel(const float* __restrict__ src,
                               __half* __restrict__ w) {
    int idx = blockIdx.x * 256 + threadIdx.x;   // float4 index
    float4 v = ((const float4*)src)[idx];
    __half2* wp = (__half2*)w;
    wp[idx * 2]     = __floats2half2_rn(v.x, v.y);
    wp[idx * 2 + 1] = __floats2half2_rn(v.z, v.w);
}

// ---------------- embedding gather ----------------
__global__ void embed_kernel(const int* __restrict__ ids,
                             const float* __restrict__ emb,
                             float* __restrict__ x) {
    int idx = blockIdx.x * 256 + threadIdx.x;
    int n = idx >> 8;
    int c = idx & 255;
    const float4* e4 = (const float4*)emb;
    ((float4*)x)[idx] = e4[(size_t)ids[n] * 256 + c];
}

// ---------------- RMSNorm -> f16 hi/lo planes ----------------
__global__ void rmsnorm_split_kernel(const float* __restrict__ x,
                                     const float* __restrict__ w,
                                     __half* __restrict__ hi,
                                     __half* __restrict__ lo) {
    int n = blockIdx.x;
    int tid = threadIdx.x;
    const float4* xr = (const float4*)(x + (size_t)n * DMODEL);
    float4 v = xr[tid];
    float ss = v.x * v.x + v.y * v.y + v.z * v.z + v.w * v.w;
#pragma unroll
    for (int o = 16; o > 0; o >>= 1) ss += __shfl_xor_sync(0xffffffffu, ss, o);
    __shared__ float red[8];
    if ((tid & 31) == 0) red[tid >> 5] = ss;
    __syncthreads();
    float tot = 0.f;
#pragma unroll
    for (int i = 0; i < 8; i++) tot += red[i];
    float r = rsqrtf(tot * (1.0f / DMODEL) + 1e-6f);
    float4 wv = ((const float4*)w)[tid];
    float ov[4] = {wv.x * v.x * r, wv.y * v.y * r, wv.z * v.z * r, wv.w * v.w * r};
    __half h[4], l[4];
#pragma unroll
    for (int j = 0; j < 4; j++) hsplit(ov[j], h[j], l[j]);
    __half2* hp = (__half2*)(hi + (size_t)n * DMODEL);
    __half2* lp = (__half2*)(lo + (size_t)n * DMODEL);
    hp[tid * 2]     = __half2{h[0], h[1]};
    hp[tid * 2 + 1] = __half2{h[2], h[3]};
    lp[tid * 2]     = __half2{l[0], l[1]};
    lp[tid * 2 + 1] = __half2{l[2], l[3]};
}

// ---------------- 2xFP16 tensor-core GEMM core ----------------
// C[N,M] = A[N,K] * W[M,K]^T; A as f16 hi/lo planes (exact), W as single f16 plane.
// EPI: 0 store fp32, 1 residual add, 2 SiLU, 3 (acc*aux) -> f16 hi/lo planes Phi/Plo
#define BK 32
#define SP 40                 // f16 per smem row (32 data + 8 pad)
#define SP32 20               // in b32 units
#define PLANE (128 * SP)      // 5120 f16
#define STAGE (3 * PLANE)     // 15360 f16 per stage (Ahi, Alo, W)
#define GEMM_SMEM (2 * STAGE * 2)  // 61440 bytes -> 2+ CTA/SM

template <int EPI>
__device__ __forceinline__ void gemm_core(
    __half* smb,
    const __half* __restrict__ Ahi, const __half* __restrict__ Alo,
    const __half* __restrict__ W,
    float* __restrict__ C, const float* __restrict__ aux,
    __half* __restrict__ Phi, __half* __restrict__ Plo,
    int K, int M, int n0, int m0) {
    int tid = threadIdx.x, lane = tid & 31, warp = tid >> 5;
    int wm = warp >> 2, wn = warp & 3;

    const __half* Ah = Ahi + (size_t)n0 * K;
    const __half* Al = Alo + (size_t)n0 * K;
    const __half* Wg = W + (size_t)m0 * K;

    float acc[4][4][4] = {};

    auto load_stage = [&](int s, int kt) {
        __half* base = smb + s * STAGE;
        const __half* gp[3] = {Ah + kt, Al + kt, Wg + kt};
#pragma unroll
        for (int pl = 0; pl < 3; pl++) {
#pragma unroll
            for (int hf = 0; hf < 2; hf++) {
                int row = hf * 64 + (tid >> 2);
                int seg = tid & 3;
                cpa16((uint32_t)__cvta_generic_to_shared(base + pl * PLANE + row * SP + seg * 8),
                      gp[pl] + (size_t)row * K + seg * 8);
            }
        }
        asm volatile("cp.async.commit_group;" ::: "memory");
    };

    load_stage(0, 0);
    int KT = K >> 5;
    int r = lane >> 2, c = lane & 3;
    for (int kt = 0; kt < KT; kt++) {
        asm volatile("cp.async.wait_group 0;" ::: "memory");
        __syncthreads();
        if (kt + 1 < KT) load_stage((kt + 1) & 1, (kt + 1) * BK);
        const __half* cb = smb + (kt & 1) * STAGE;
        const uint32_t* aH = (const uint32_t*)(cb);
        const uint32_t* aL = (const uint32_t*)(cb + PLANE);
        const uint32_t* wP = (const uint32_t*)(cb + 2 * PLANE);
#pragma unroll
        for (int ks = 0; ks < 2; ks++) {
            int kb = ks * 8 + c;
            uint32_t ah[4][4], al[4][4], b[4][2];
#pragma unroll
            for (int i = 0; i < 4; i++) {
                int m = wm * 64 + i * 16 + r;
                ah[i][0] = aH[m * SP32 + kb];
                ah[i][1] = aH[(m + 8) * SP32 + kb];
                ah[i][2] = aH[m * SP32 + kb + 4];
                ah[i][3] = aH[(m + 8) * SP32 + kb + 4];
                al[i][0] = aL[m * SP32 + kb];
                al[i][1] = aL[(m + 8) * SP32 + kb];
                al[i][2] = aL[m * SP32 + kb + 4];
                al[i][3] = aL[(m + 8) * SP32 + kb + 4];
            }
#pragma unroll
            for (int j = 0; j < 4; j++) {
                int n = wn * 32 + j * 8 + r;
                b[j][0] = wP[n * SP32 + kb];
                b[j][1] = wP[n * SP32 + kb + 4];
            }
#pragma unroll
            for (int i = 0; i < 4; i++)
#pragma unroll
                for (int j = 0; j < 4; j++) {
                    mma_f16(acc[i][j], ah[i], b[j]);
                    mma_f16(acc[i][j], al[i], b[j]);
                }
        }
        __syncthreads();
    }

    // epilogue
    int rr = lane >> 2, cc = (lane & 3) * 2;
#pragma unroll
    for (int i = 0; i < 4; i++) {
#pragma unroll
        for (int half = 0; half < 2; half++) {
            int grow = n0 + wm * 64 + i * 16 + rr + half * 8;
#pragma unroll
            for (int j = 0; j < 4; j++) {
                int gcol = m0 + wn * 32 + j * 8 + cc;
                size_t off = (size_t)grow * M + gcol;
                float2 v = make_float2(acc[i][j][half * 2], acc[i][j][half * 2 + 1]);
                if (EPI == 1) {
                    float2 rv = *(const float2*)(aux + off);
                    v.x += rv.x; v.y += rv.y;
                } else if (EPI == 2) {
                    v.x = v.x / (1.0f + __expf(-v.x));
                    v.y = v.y / (1.0f + __expf(-v.y));
                } else if (EPI == 3) {
                    float2 rv = *(const float2*)(aux + off);
                    v.x *= rv.x; v.y *= rv.y;
                    __half h0, h1, l0, l1;
                    hsplit(v.x, h0, l0);
                    hsplit(v.y, h1, l1);
                    *(__half2*)(Phi + off) = __half2{h0, h1};
                    *(__half2*)(Plo + off) = __half2{l0, l1};
                }
                if (EPI != 3) *(float2*)(C + off) = v;
            }
        }
    }
}

// Standard GEMM: grid (NTOK/128 fast, M/128)
template <int EPI>
__global__ __launch_bounds__(256) void gemm_f16c(
    const __half* __restrict__ Ahi, const __half* __restrict__ Alo,
    const __half* __restrict__ W,
    float* __restrict__ C, const float* __restrict__ aux,
    __half* __restrict__ Phi, __half* __restrict__ Plo,
    int K, int M) {
    extern __shared__ __half smb[];
    gemm_core<EPI>(smb, Ahi, Alo, W, C, aux, Phi, Plo, K, M,
                   blockIdx.x * 128, blockIdx.y * 128);
}

// Fused QKV GEMM: grid (16, 12): y<8 -> Q, y in {8,9} -> K, y in {10,11} -> V
__global__ __launch_bounds__(256) void gemm_qkv(
    const __half* __restrict__ Ahi, const __half* __restrict__ Alo,
    const __half* __restrict__ Qw, const __half* __restrict__ Kw,
    const __half* __restrict__ Vw,
    float* __restrict__ Cq, float* __restrict__ Ck, float* __restrict__ Cv) {
    extern __shared__ __half smb[];
    int y = blockIdx.y;
    const __half* w;
    float* C;
    int m0, M;
    if (y < 8)       { w = Qw; C = Cq; m0 = y * 128;        M = DMODEL; }
    else if (y < 10) { w = Kw; C = Ck; m0 = (y - 8) * 128;  M = KVDIM; }
    else             { w = Vw; C = Cv; m0 = (y - 10) * 128; M = KVDIM; }
    gemm_core<0>(smb, Ahi, Alo, w, C, nullptr, nullptr, nullptr, DMODEL, M,
                 blockIdx.x * 128, m0);
}

// ---------------- causal flash attention (fp32, GQA, fused RoPE) -> f16 planes ----------------
__global__ __launch_bounds__(256) void attn_kernel(
    const float* __restrict__ Q, const float* __restrict__ K,
    const float* __restrict__ V,
    __half* __restrict__ Ohi, __half* __restrict__ Olo) {
    __shared__ float Qs[64][64];
    __shared__ float Ks[32][68];
    __shared__ float Vs[32][64];
    __shared__ float Ps[64][33];
    int bh = blockIdx.y;
    int b = bh >> 4;
    int h = bh & 15;
    int kvh = h >> 2;
    int q0 = blockIdx.x * 64;
    int tid = threadIdx.x;
    int lane = tid & 31, warp = tid >> 5;
    const float scale = 0.125f;

    const float* Qbase = Q + ((size_t)(b * SEQ + q0)) * DMODEL + h * HEADDIM;
    for (int i = tid; i < 64 * 8; i += 256) {
        int row = i >> 3, c4 = i & 7;
        int t = q0 + row;
        const float* qp = Qbase + (size_t)row * DMODEL;
        float4 x1 = *(const float4*)(qp + c4 * 4);
        float4 x2 = *(const float4*)(qp + c4 * 4 + 32);
        float4 o1, o2;
        float* x1p = &x1.x; float* x2p = &x2.x;
        float* o1p = &o1.x; float* o2p = &o2.x;
#pragma unroll
        for (int j = 0; j < 4; j++) {
            int d = c4 * 4 + j;
            float inv = 1.0f / powf(10000.0f, (float)d * (1.0f / 32.0f));
            float s, c;
            sincosf((float)t * inv, &s, &c);
            o1p[j] = (x1p[j] * c - x2p[j] * s) * scale;
            o2p[j] = (x2p[j] * c + x1p[j] * s) * scale;
        }
        *(float4*)&Qs[row][c4 * 4] = o1;
        *(float4*)&Qs[row][c4 * 4 + 32] = o2;
    }

    float m[8], l[8], acc0[8], acc1[8];
#pragma unroll
    for (int r = 0; r < 8; r++) { m[r] = -1e30f; l[r] = 0.f; acc0[r] = 0.f; acc1[r] = 0.f; }

    int kend = q0 + 64;
    for (int kc = 0; kc < kend; kc += 32) {
        __syncthreads();
        const float* Kbase = K + ((size_t)(b * SEQ + kc)) * KVDIM + kvh * HEADDIM;
        const float* Vbase = V + ((size_t)(b * SEQ + kc)) * KVDIM + kvh * HEADDIM;
        for (int i = tid; i < 32 * 8; i += 256) {
            int row = i >> 3, c4 = i & 7;
            int t = kc + row;
            const float* kp = Kbase + (size_t)row * KVDIM;
            float4 x1 = *(const float4*)(kp + c4 * 4);
            float4 x2 = *(const float4*)(kp + c4 * 4 + 32);
            float4 o1, o2;
            float* x1p = &x1.x; float* x2p = &x2.x;
            float* o1p = &o1.x; float* o2p = &o2.x;
#pragma unroll
            for (int j = 0; j < 4; j++) {
                int d = c4 * 4 + j;
                float inv = 1.0f / powf(10000.0f, (float)d * (1.0f / 32.0f));
                float s, c;
                sincosf((float)t * inv, &s, &c);
                o1p[j] = x1p[j] * c - x2p[j] * s;
                o2p[j] = x2p[j] * c + x1p[j] * s;
            }
            *(float4*)&Ks[row][c4 * 4] = o1;
            *(float4*)&Ks[row][c4 * 4 + 32] = o2;
        }
        for (int i = tid; i < 32 * 16; i += 256) {
            int row = i >> 4, c = (i & 15) * 4;
            float4 vv = *(const float4*)(Vbase + (size_t)row * KVDIM + c);
            *(float4*)&Vs[row][c] = vv;
        }
        __syncthreads();

        float s[8] = {0.f, 0.f, 0.f, 0.f, 0.f, 0.f, 0.f, 0.f};
#pragma unroll
        for (int d4 = 0; d4 < 16; d4++) {
            float4 kv = *(const float4*)&Ks[lane][d4 * 4];
#pragma unroll
            for (int r = 0; r < 8; r++) {
                float4 qv = *(const float4*)&Qs[warp * 8 + r][d4 * 4];
                s[r] += qv.x * kv.x + qv.y * kv.y + qv.z * kv.z + qv.w * kv.w;
            }
        }
        int key = kc + lane;
#pragma unroll
        for (int r = 0; r < 8; r++) {
            int qrow = q0 + warp * 8 + r;
            float sv = (key <= qrow) ? s[r] : -1e30f;
            float mx = sv;
#pragma unroll
            for (int o = 16; o > 0; o >>= 1) mx = fmaxf(mx, __shfl_xor_sync(0xffffffffu, mx, o));
            float mn = fmaxf(m[r], mx);
            float p = __expf(sv - mn);
            float cor = __expf(m[r] - mn);
            float ps = p;
#pragma unroll
            for (int o = 16; o > 0; o >>= 1) ps += __shfl_xor_sync(0xffffffffu, ps, o);
            l[r] = l[r] * cor + ps;
            acc0[r] *= cor;
            acc1[r] *= cor;
            m[r] = mn;
            Ps[warp * 8 + r][lane] = p;
        }
        __syncwarp();
#pragma unroll 4
        for (int j = 0; j < 32; j++) {
            float v0 = Vs[j][lane];
            float v1 = Vs[j][lane + 32];
#pragma unroll
            for (int r = 0; r < 8; r++) {
                float p = Ps[warp * 8 + r][j];
                acc0[r] += p * v0;
                acc1[r] += p * v1;
            }
        }
    }

    size_t obase = ((size_t)(b * SEQ + q0)) * DMODEL + h * HEADDIM;
#pragma unroll
    for (int r = 0; r < 8; r++) {
        int row = warp * 8 + r;
        float inv = 1.0f / l[r];
        float v0 = acc0[r] * inv, v1 = acc1[r] * inv;
        __half h0, h1, l0, l1;
        hsplit(v0, h0, l0);
        hsplit(v1, h1, l1);
        size_t o0 = obase + (size_t)row * DMODEL + lane;
        Ohi[o0] = h0;  Olo[o0] = l0;
        Ohi[o0 + 32] = h1;  Olo[o0 + 32] = l1;
    }
}

// ---------------- host orchestration ----------------
extern "C" void kernel_launch(void* const* d_in, const int* in_sizes, int n_in,
                              void* d_out, int out_size) {
    const int*   ids = (const int*)d_in[0];
    const float* emb = (const float*)d_in[1];
    const float* ln1 = (const float*)d_in[2];
    const float* qw  = (const float*)d_in[3];
    const float* kw  = (const float*)d_in[4];
    const float* vw  = (const float*)d_in[5];
    const float* ow  = (const float*)d_in[6];
    const float* ln2 = (const float*)d_in[7];
    const float* w1  = (const float*)d_in[8];
    const float* w2  = (const float*)d_in[9];
    const float* w3  = (const float*)d_in[10];
    const float* lnf = (const float*)d_in[11];
    float* out = (float*)d_out;

    float *x, *q, *k, *v, *gate;
    __half *hh, *hl, *oh, *ol, *uph, *upl;
    __half *embw, *qww, *kww, *vww, *oww, *w1w, *w2w, *w3w;
    cudaGetSymbolAddress((void**)&x, g_x);
    cudaGetSymbolAddress((void**)&q, g_q);
    cudaGetSymbolAddress((void**)&k, g_k);
    cudaGetSymbolAddress((void**)&v, g_v);
    cudaGetSymbolAddress((void**)&gate, g_gate);
    cudaGetSymbolAddress((void**)&hh, g_h_h);
    cudaGetSymbolAddress((void**)&hl, g_h_l);
    cudaGetSymbolAddress((void**)&oh, g_o_h);
    cudaGetSymbolAddress((void**)&ol, g_o_l);
    cudaGetSymbolAddress((void**)&uph, g_up_h);
    cudaGetSymbolAddress((void**)&upl, g_up_l);
    cudaGetSymbolAddress((void**)&embw, s_emb_w);
    cudaGetSymbolAddress((void**)&qww, s_qw_w);
    cudaGetSymbolAddress((void**)&kww, s_kw_w);
    cudaGetSymbolAddress((void**)&vww, s_vw_w);
    cudaGetSymbolAddress((void**)&oww, s_ow_w);
    cudaGetSymbolAddress((void**)&w1w, s_w1_w);
    cudaGetSymbolAddress((void**)&w2w, s_w2_w);
    cudaGetSymbolAddress((void**)&w3w, s_w3_w);

    cudaFuncSetAttribute(gemm_f16c<0>, cudaFuncAttributeMaxDynamicSharedMemorySize, GEMM_SMEM);
    cudaFuncSetAttribute(gemm_f16c<1>, cudaFuncAttributeMaxDynamicSharedMemorySize, GEMM_SMEM);
    cudaFuncSetAttribute(gemm_f16c<2>, cudaFuncAttributeMaxDynamicSharedMemorySize, GEMM_SMEM);
    cudaFuncSetAttribute(gemm_f16c<3>, cudaFuncAttributeMaxDynamicSharedMemorySize, GEMM_SMEM);
    cudaFuncSetAttribute(gemm_qkv,     cudaFuncAttributeMaxDynamicSharedMemorySize, GEMM_SMEM);

    // pre-pass: weights -> single f16 plane
    split_w_kernel<<<EMB_N / 1024, 256>>>(emb, embw);
    split_w_kernel<<<QW_N / 1024, 256>>>(qw, qww);
    split_w_kernel<<<KW_N / 1024, 256>>>(kw, kww);
    split_w_kernel<<<KW_N / 1024, 256>>>(vw, vww);
    split_w_kernel<<<QW_N / 1024, 256>>>(ow, oww);
    split_w_kernel<<<W1_N / 1024, 256>>>(w1, w1w);
    split_w_kernel<<<W1_N / 1024, 256>>>(w2, w2w);
    split_w_kernel<<<W1_N / 1024, 256>>>(w3, w3w);

    embed_kernel<<<NTOK, 256>>>(ids, emb, x);

    const int TB = NTOK / 128;   // 16 token blocks: FAST grid dim (weight L2 reuse)
    for (int l = 0; l < NLAYER; l++) {
        size_t qo = (size_t)l * DMODEL * DMODEL;
        size_t ko = (size_t)l * KVDIM * DMODEL;
        size_t fo = (size_t)l * FFN * DMODEL;

        rmsnorm_split_kernel<<<NTOK, 256>>>(x, ln1 + l * DMODEL, hh, hl);
        gemm_qkv<<<dim3(TB, 12), 256, GEMM_SMEM>>>(
            hh, hl, qww + qo, kww + ko, vww + ko, q, k, v);
        attn_kernel<<<dim3(SEQ / 64, 2 * NHEAD), 256>>>(q, k, v, oh, ol);
        gemm_f16c<1><<<dim3(TB, DMODEL / 128), 256, GEMM_SMEM>>>(
            oh, ol, oww + qo, x, x, nullptr, nullptr, DMODEL, DMODEL);
        rmsnorm_split_kernel<<<NTOK, 256>>>(x, ln2 + l * DMODEL, hh, hl);
        gemm_f16c<2><<<dim3(TB, FFN / 128), 256, GEMM_SMEM>>>(
            hh, hl, w1w + fo, gate, nullptr, nullptr, nullptr, DMODEL, FFN);
        gemm_f16c<3><<<dim3(TB, FFN / 128), 256, GEMM_SMEM>>>(
            hh, hl, w3w + fo, nullptr, gate, uph, upl, DMODEL, FFN);
        gemm_f16c<1><<<dim3(TB, DMODEL / 128), 256, GEMM_SMEM>>>(
            uph, upl, w2w + fo, x, x, nullptr, nullptr, FFN, DMODEL);
    }

    rmsnorm_split_kernel<<<NTOK, 256>>>(x, lnf, hh, hl);
    gemm_f16c<0><<<dim3(TB, VOCAB / 128), 256, GEMM_SMEM>>>(
        hh, hl, embw, out, nullptr, nullptr, nullptr, DMODEL, VOCAB);
}